// round 11
// baseline (speedup 1.0000x reference)
#include <cuda_runtime.h>
#include <cstdint>

// ---------------------------------------------------------------------------
// GIN (2 layers) on GB300 — gather FUSED into the 2-GEMM MLP kernels.
// Each CTA: gather its 64 rows (x + neighbor sum) straight into splatted SMEM,
// then relu(A@W1+b1) in SMEM, then act(t@W2+b2) -> global. f32x2 FFMA2
// microkernel, cp.async W streaming, As/T1 aliasing, 2 CTAs/SM.
// ---------------------------------------------------------------------------

#define NMAX 50000
#define EMAX 800000
#define CIN  64
#define CHID 128
#define SCAN_BS 1024
#define MAXPART 256

__device__ float g_h[NMAX * CHID];

__device__ int g_deg   [NMAX];
__device__ int g_offs  [NMAX + 1];
__device__ int g_cursor[NMAX];
__device__ int g_csr   [EMAX];
__device__ int g_part  [MAXPART];
__device__ unsigned g_is64;

// ======================= small PTX helpers =================================
__device__ __forceinline__ uint32_t smem_u32(const void* p) {
    uint32_t a;
    asm("{ .reg .u64 t; cvta.to.shared.u64 t, %1; cvt.u32.u64 %0, t; }"
        : "=r"(a) : "l"(p));
    return a;
}
#define FMA2(acc_, a_, b_) \
    asm("fma.rn.f32x2 %0, %1, %2, %0;" : "+l"(acc_) : "l"(a_), "l"(b_))
#define UNPK(lo_, hi_, p_) \
    asm("mov.b64 {%0, %1}, %2;" : "=r"(lo_), "=r"(hi_) : "l"(p_))
#define CP_WAIT0() asm volatile("cp.async.wait_group 0;" ::: "memory")
#define CP_WAIT1() asm volatile("cp.async.wait_group 1;" ::: "memory")

template <int CO>
__device__ __forceinline__ void prefetch_w(uint32_t wb_dst, const float* __restrict__ Wsrc,
                                           int kb, int tid) {
    constexpr int IT = (32 * CO / 4) / 256;
    const float* base = Wsrc + (long long)kb * 32 * CO;
#pragma unroll
    for (int t = 0; t < IT; ++t) {
        int idx = tid + t * 256;
        int row = idx / (CO / 4);
        int c4  = idx % (CO / 4);
        uint32_t dst = wb_dst + (uint32_t)(row * CO + c4 * 4) * 4u;
        const float* src = base + row * CO + c4 * 4;
        asm volatile("cp.async.cg.shared.global [%0], [%1], 16;" :: "r"(dst), "l"(src));
    }
    asm volatile("cp.async.commit_group;" ::: "memory");
}

// ======================= CSR build =========================================
__global__ void detect_zero_kernel(const unsigned* __restrict__ ei_u32,
                                   int* __restrict__ deg, int N) {
    int i = blockIdx.x * blockDim.x + threadIdx.x;
    if (i < N) deg[i] = 0;
    if (blockIdx.x == gridDim.x - 1 && threadIdx.x < 32) {
        unsigned acc = 0;
#pragma unroll
        for (int t = 0; t < 16; ++t)
            acc |= ei_u32[2 * (threadIdx.x + t * 32) + 1];
#pragma unroll
        for (int o = 16; o > 0; o >>= 1)
            acc |= __shfl_down_sync(0xffffffffu, acc, o);
        if (threadIdx.x == 0) g_is64 = (acc == 0u) ? 1u : 0u;
    }
}
__global__ void hist_kernel(const void* __restrict__ ei, int* __restrict__ deg, int E) {
    int e = blockIdx.x * blockDim.x + threadIdx.x;
    if (e >= E) return;
    int d = g_is64 ? (int)((const long long*)ei)[E + e] : ((const int*)ei)[E + e];
    atomicAdd(&deg[d], 1);
}
__global__ void scan1_kernel(const int* __restrict__ deg, int* __restrict__ offs,
                             int* __restrict__ part, int N) {
    __shared__ int wsum[32];
    const int tid = threadIdx.x, lane = tid & 31, wid = tid >> 5;
    int i = blockIdx.x * SCAN_BS + tid;
    int v = (i < N) ? deg[i] : 0;
    int x = v;
#pragma unroll
    for (int o = 1; o < 32; o <<= 1) {
        int y = __shfl_up_sync(0xffffffffu, x, o);
        if (lane >= o) x += y;
    }
    if (lane == 31) wsum[wid] = x;
    __syncthreads();
    if (wid == 0) {
        int w = wsum[lane];
#pragma unroll
        for (int o = 1; o < 32; o <<= 1) {
            int y = __shfl_up_sync(0xffffffffu, w, o);
            if (lane >= o) w += y;
        }
        wsum[lane] = w;
    }
    __syncthreads();
    int warpoff = (wid > 0) ? wsum[wid - 1] : 0;
    if (i < N) offs[i] = warpoff + x - v;
    if (tid == SCAN_BS - 1) part[blockIdx.x] = warpoff + x;
}
__global__ void scan23_kernel(int* __restrict__ offs, int* __restrict__ cursor,
                              const int* __restrict__ part, int nblk, int N) {
    __shared__ int soff;
    const int tid = threadIdx.x;
    if (tid < 32) {
        int s = 0;
        for (int j = tid; j < nblk; j += 32)
            if (j < (int)blockIdx.x) s += part[j];
#pragma unroll
        for (int o = 16; o > 0; o >>= 1) s += __shfl_down_sync(0xffffffffu, s, o);
        if (tid == 0) soff = s;
    }
    __syncthreads();
    int i = blockIdx.x * SCAN_BS + tid;
    if (i < N) {
        int v = offs[i] + soff;
        offs[i] = v;
        cursor[i] = v;
    }
    if (blockIdx.x == gridDim.x - 1 && tid < 32) {
        int s = 0;
        for (int j = tid; j < nblk; j += 32) s += part[j];
#pragma unroll
        for (int o = 16; o > 0; o >>= 1) s += __shfl_down_sync(0xffffffffu, s, o);
        if (tid == 0) offs[N] = s;
    }
}
__global__ void fill_kernel(const void* __restrict__ ei, int* __restrict__ cursor,
                            int* __restrict__ csr, int E) {
    int e = blockIdx.x * blockDim.x + threadIdx.x;
    if (e >= E) return;
    int s, d;
    if (g_is64) {
        const long long* p = (const long long*)ei;
        s = (int)p[e];
        d = (int)p[E + e];
    } else {
        const int* p = (const int*)ei;
        s = p[e];
        d = p[E + e];
    }
    int pos = atomicAdd(&cursor[d], 1);
    csr[pos] = s;
}

// ======================= fused gather + 2-GEMM MLP =========================
// Out[N,CO2] = act2(relu((feat + nbr_sum(feat))[tile] @ W1 + b1) @ W2 + b2)
// CTA gathers its own 64 rows straight into splatted As. As/T1 alias.
template <int CI, int CO2, int RELU2>
__global__ void __launch_bounds__(256, 2)
mlp_fused_kernel(const float* __restrict__ feat,
                 const int* __restrict__ offs, const int* __restrict__ csr,
                 const float* __restrict__ W1, const float* __restrict__ b1,
                 const float* __restrict__ W2, const float* __restrict__ b2,
                 float* __restrict__ Out, int Nrows) {
    constexpr int SA  = 132;
    constexpr int KB1 = CI / 32;
    constexpr int KB2 = 128 / 32;
    constexpr int NG  = CO2 / 64;

    extern __shared__ float sm[];
    float* As = sm;                    // CI x SA   (aliases T1)
    float* T1 = sm;                    // 128 x SA
    float* Wb = sm + 128 * SA;         // 2 x 32 x 128 W double buffer
    const uint32_t wb_addr = smem_u32(Wb);
    constexpr uint32_t WBUF_BYTES = 32 * 128 * 4;

    const int tid = threadIdx.x;
    const int tr  = tid >> 4;
    const int tc  = tid & 15;
    const long long rowBase = (long long)blockIdx.x * 64;

    prefetch_w<128>(wb_addr, W1, 0, tid);

    // ---- fused gather prologue: As = splat(feat[row] + sum_nbr feat[nbr]) ----
    if (CI == 64) {
        const float4* f4 = (const float4*)feat;
        const int l16 = tid & 15, hw = tid >> 4;
#pragma unroll
        for (int r = 0; r < 4; ++r) {
            int m = hw + r * 16;
            long long row = rowBase + m;
            float4 acc = make_float4(0.f, 0.f, 0.f, 0.f);
            if (row < Nrows) {
                acc = f4[row * 16 + l16];
                int s = offs[row], e = offs[row + 1];
                int k2 = s;
                for (; k2 + 1 < e; k2 += 2) {
                    int j0 = __ldg(&csr[k2]);
                    int j1 = __ldg(&csr[k2 + 1]);
                    float4 v0 = f4[(long long)j0 * 16 + l16];
                    float4 v1 = f4[(long long)j1 * 16 + l16];
                    acc.x += v0.x + v1.x; acc.y += v0.y + v1.y;
                    acc.z += v0.z + v1.z; acc.w += v0.w + v1.w;
                }
                if (k2 < e) {
                    int j = __ldg(&csr[k2]);
                    float4 v = f4[(long long)j * 16 + l16];
                    acc.x += v.x; acc.y += v.y; acc.z += v.z; acc.w += v.w;
                }
            }
            int c0 = l16 * 4;
            *(float2*)&As[(c0 + 0) * SA + 2 * m] = make_float2(acc.x, acc.x);
            *(float2*)&As[(c0 + 1) * SA + 2 * m] = make_float2(acc.y, acc.y);
            *(float2*)&As[(c0 + 2) * SA + 2 * m] = make_float2(acc.z, acc.z);
            *(float2*)&As[(c0 + 3) * SA + 2 * m] = make_float2(acc.w, acc.w);
        }
    } else {
        const float4* f4 = (const float4*)feat;
        const int lane = tid & 31, w = tid >> 5;
#pragma unroll
        for (int r = 0; r < 8; ++r) {
            int m = w + r * 8;
            long long row = rowBase + m;
            float4 acc = make_float4(0.f, 0.f, 0.f, 0.f);
            if (row < Nrows) {
                acc = f4[row * 32 + lane];
                int s = offs[row], e = offs[row + 1];
                int k2 = s;
                for (; k2 + 1 < e; k2 += 2) {
                    int j0 = __ldg(&csr[k2]);
                    int j1 = __ldg(&csr[k2 + 1]);
                    float4 v0 = f4[(long long)j0 * 32 + lane];
                    float4 v1 = f4[(long long)j1 * 32 + lane];
                    acc.x += v0.x + v1.x; acc.y += v0.y + v1.y;
                    acc.z += v0.z + v1.z; acc.w += v0.w + v1.w;
                }
                if (k2 < e) {
                    int j = __ldg(&csr[k2]);
                    float4 v = f4[(long long)j * 32 + lane];
                    acc.x += v.x; acc.y += v.y; acc.z += v.z; acc.w += v.w;
                }
            }
            int c0 = lane * 4;
            *(float2*)&As[(c0 + 0) * SA + 2 * m] = make_float2(acc.x, acc.x);
            *(float2*)&As[(c0 + 1) * SA + 2 * m] = make_float2(acc.y, acc.y);
            *(float2*)&As[(c0 + 2) * SA + 2 * m] = make_float2(acc.z, acc.z);
            *(float2*)&As[(c0 + 3) * SA + 2 * m] = make_float2(acc.w, acc.w);
        }
    }

    unsigned long long acc[4][4];
#pragma unroll
    for (int i = 0; i < 4; ++i)
#pragma unroll
        for (int j = 0; j < 4; ++j) acc[i][j] = 0ull;

    // ---------------- stage 1: acc = A @ W1 ----------------
#pragma unroll
    for (int kb = 0; kb < KB1; ++kb) {
        if (kb + 1 < KB1) {
            prefetch_w<128>(wb_addr + ((kb + 1) & 1) * WBUF_BYTES, W1, kb + 1, tid);
            CP_WAIT1();
        } else {
            CP_WAIT0();
        }
        __syncthreads();
        const float* Bs  = Wb + (kb & 1) * (32 * 128);
        const float* Asb = As + kb * 32 * SA;
#pragma unroll
        for (int k = 0; k < 32; ++k) {
            ulonglong2 aa = *(const ulonglong2*)&Asb[k * SA + tr * 8];
            ulonglong2 ab = *(const ulonglong2*)&Asb[k * SA + tr * 8 + 4];
            ulonglong2 b0 = *(const ulonglong2*)&Bs[k * 128 + tc * 4];
            ulonglong2 b1v = *(const ulonglong2*)&Bs[k * 128 + 64 + tc * 4];
            FMA2(acc[0][0], aa.x, b0.x); FMA2(acc[0][1], aa.x, b0.y);
            FMA2(acc[0][2], aa.x, b1v.x); FMA2(acc[0][3], aa.x, b1v.y);
            FMA2(acc[1][0], aa.y, b0.x); FMA2(acc[1][1], aa.y, b0.y);
            FMA2(acc[1][2], aa.y, b1v.x); FMA2(acc[1][3], aa.y, b1v.y);
            FMA2(acc[2][0], ab.x, b0.x); FMA2(acc[2][1], ab.x, b0.y);
            FMA2(acc[2][2], ab.x, b1v.x); FMA2(acc[2][3], ab.x, b1v.y);
            FMA2(acc[3][0], ab.y, b0.x); FMA2(acc[3][1], ab.y, b0.y);
            FMA2(acc[3][2], ab.y, b1v.x); FMA2(acc[3][3], ab.y, b1v.y);
        }
        __syncthreads();   // all As reads done -> safe to overwrite (T1 alias)
    }

    prefetch_w<CO2>(wb_addr, W2, 0, tid);

    // ---- stage-1 epilogue: bias + relu, splat into T1 (aliasing As) ----
    {
        float bb[8];
#pragma unroll
        for (int e = 0; e < 4; ++e) {
            bb[e]     = __ldg(&b1[tc * 4 + e]);
            bb[4 + e] = __ldg(&b1[64 + tc * 4 + e]);
        }
#pragma unroll
        for (int i = 0; i < 4; ++i) {
            int m2 = 2 * (tr * 4 + i);
#pragma unroll
            for (int g = 0; g < 2; ++g)
#pragma unroll
                for (int jp = 0; jp < 2; ++jp) {
                    uint32_t lo, hi;
                    UNPK(lo, hi, acc[i][g * 2 + jp]);
                    float v0 = fmaxf(__uint_as_float(lo) + bb[g * 4 + jp * 2 + 0], 0.f);
                    float v1 = fmaxf(__uint_as_float(hi) + bb[g * 4 + jp * 2 + 1], 0.f);
                    int c = g * 64 + tc * 4 + jp * 2;
                    *(float2*)&T1[(c + 0) * SA + m2] = make_float2(v0, v0);
                    *(float2*)&T1[(c + 1) * SA + m2] = make_float2(v1, v1);
                }
        }
    }
    __syncthreads();

    // ---------------- stage 2: out = T1 @ W2 ----------------
    unsigned long long acc2[4][2 * NG];
#pragma unroll
    for (int i = 0; i < 4; ++i)
#pragma unroll
        for (int j = 0; j < 2 * NG; ++j) acc2[i][j] = 0ull;

#pragma unroll
    for (int kb = 0; kb < KB2; ++kb) {
        if (kb + 1 < KB2) {
            prefetch_w<CO2>(wb_addr + ((kb + 1) & 1) * WBUF_BYTES, W2, kb + 1, tid);
            CP_WAIT1();
        } else {
            CP_WAIT0();
        }
        __syncthreads();
        const float* Bs = Wb + (kb & 1) * (32 * 128);
        const float* Tb = T1 + kb * 32 * SA;
#pragma unroll
        for (int k = 0; k < 32; ++k) {
            ulonglong2 aa = *(const ulonglong2*)&Tb[k * SA + tr * 8];
            ulonglong2 ab = *(const ulonglong2*)&Tb[k * SA + tr * 8 + 4];
            ulonglong2 b0 = *(const ulonglong2*)&Bs[k * CO2 + tc * 4];
            FMA2(acc2[0][0], aa.x, b0.x); FMA2(acc2[0][1], aa.x, b0.y);
            FMA2(acc2[1][0], aa.y, b0.x); FMA2(acc2[1][1], aa.y, b0.y);
            FMA2(acc2[2][0], ab.x, b0.x); FMA2(acc2[2][1], ab.x, b0.y);
            FMA2(acc2[3][0], ab.y, b0.x); FMA2(acc2[3][1], ab.y, b0.y);
            if (NG == 2) {
                ulonglong2 b1v = *(const ulonglong2*)&Bs[k * CO2 + 64 + tc * 4];
                FMA2(acc2[0][2], aa.x, b1v.x); FMA2(acc2[0][3], aa.x, b1v.y);
                FMA2(acc2[1][2], aa.y, b1v.x); FMA2(acc2[1][3], aa.y, b1v.y);
                FMA2(acc2[2][2], ab.x, b1v.x); FMA2(acc2[2][3], ab.x, b1v.y);
                FMA2(acc2[3][2], ab.y, b1v.x); FMA2(acc2[3][3], ab.y, b1v.y);
            }
        }
        __syncthreads();
    }

    // ---- final epilogue ----
    {
        float bb[4 * NG];
#pragma unroll
        for (int g = 0; g < NG; ++g)
#pragma unroll
            for (int e = 0; e < 4; ++e)
                bb[g * 4 + e] = __ldg(&b2[g * 64 + tc * 4 + e]);
#pragma unroll
        for (int i = 0; i < 4; ++i) {
            long long row = rowBase + tr * 4 + i;
            if (row >= Nrows) continue;
#pragma unroll
            for (int g = 0; g < NG; ++g) {
                uint32_t l0, h0, l1, h1;
                UNPK(l0, h0, acc2[i][g * 2 + 0]);
                UNPK(l1, h1, acc2[i][g * 2 + 1]);
                float4 o;
                o.x = __uint_as_float(l0) + bb[g * 4 + 0];
                o.y = __uint_as_float(h0) + bb[g * 4 + 1];
                o.z = __uint_as_float(l1) + bb[g * 4 + 2];
                o.w = __uint_as_float(h1) + bb[g * 4 + 3];
                if (RELU2) {
                    o.x = fmaxf(o.x, 0.f); o.y = fmaxf(o.y, 0.f);
                    o.z = fmaxf(o.z, 0.f); o.w = fmaxf(o.w, 0.f);
                }
                *(float4*)(Out + row * CO2 + g * 64 + tc * 4) = o;
            }
        }
    }
}

// ---------------------------------------------------------------------------
extern "C" void kernel_launch(void* const* d_in, const int* in_sizes, int n_in,
                              void* d_out, int out_size) {
    const float* x  = (const float*)d_in[0];
    const void*  ei = d_in[1];
    const float* W1 = (const float*)d_in[2];
    const float* b1 = (const float*)d_in[3];
    const float* W2 = (const float*)d_in[4];
    const float* b2 = (const float*)d_in[5];
    const float* W3 = (const float*)d_in[6];
    const float* b3 = (const float*)d_in[7];
    const float* W4 = (const float*)d_in[8];
    const float* b4 = (const float*)d_in[9];

    const int N = in_sizes[0] / CIN;
    const int E = in_sizes[1] / 2;

    float* h;
    cudaGetSymbolAddress((void**)&h, g_h);
    int *deg, *offs, *cursor, *csr, *part;
    cudaGetSymbolAddress((void**)&deg,    g_deg);
    cudaGetSymbolAddress((void**)&offs,   g_offs);
    cudaGetSymbolAddress((void**)&cursor, g_cursor);
    cudaGetSymbolAddress((void**)&csr,    g_csr);
    cudaGetSymbolAddress((void**)&part,   g_part);

    float* out = (float*)d_out;
    const int rtiles      = (N + 63) / 64;
    const int edge_blocks = (E + 255) / 256;
    const int scan_blocks = (N + SCAN_BS - 1) / SCAN_BS;

    const int smem_mlp = (128 * 132 + 2 * 32 * 128) * 4;   // ~100 KB
    cudaFuncSetAttribute(mlp_fused_kernel<CIN,  CHID, 1>,
                         cudaFuncAttributeMaxDynamicSharedMemorySize, smem_mlp);
    cudaFuncSetAttribute(mlp_fused_kernel<CHID, CIN,  0>,
                         cudaFuncAttributeMaxDynamicSharedMemorySize, smem_mlp);

    // ---- CSR build (5 launches) ----
    detect_zero_kernel<<<(N + 255) / 256, 256>>>((const unsigned*)ei, deg, N);
    hist_kernel<<<edge_blocks, 256>>>(ei, deg, E);
    scan1_kernel<<<scan_blocks, SCAN_BS>>>(deg, offs, part, N);
    scan23_kernel<<<scan_blocks, SCAN_BS>>>(offs, cursor, part, scan_blocks, N);
    fill_kernel<<<edge_blocks, 256>>>(ei, cursor, csr, E);

    // ---- Layer 1: fused gather + MLP (relu outer) ----
    mlp_fused_kernel<CIN,  CHID, 1><<<rtiles, 256, smem_mlp>>>(
        x, offs, csr, W1, b1, W2, b2, h, N);

    // ---- Layer 2: fused gather + MLP (no outer relu) ----
    mlp_fused_kernel<CHID, CIN,  0><<<rtiles, 256, smem_mlp>>>(
        h, offs, csr, W3, b3, W4, b4, out, N);
}

// round 12
// speedup vs baseline: 1.0134x; 1.0134x over previous
#include <cuda_runtime.h>
#include <cstdint>

// ---------------------------------------------------------------------------
// GIN (2 layers) on GB300 — CSR-gather aggregation + fused 2-GEMM MLP kernels.
// f32x2 (FFMA2) microkernels, 2-deep cp.async W pipeline, As/T1 SMEM aliasing
// (2 CTAs/SM). Separate gather kernels (full node-level parallelism).
// ---------------------------------------------------------------------------

#define NMAX 50000
#define EMAX 800000
#define CIN  64
#define CHID 128
#define SCAN_BS 1024
#define MAXPART 256

__device__ float g_h1pre[NMAX * CIN];
__device__ float g_h    [NMAX * CHID];
__device__ float g_h2pre[NMAX * CHID];

__device__ int g_deg   [NMAX];
__device__ int g_offs  [NMAX + 1];
__device__ int g_cursor[NMAX];
__device__ int g_csr   [EMAX];
__device__ int g_part  [MAXPART];
__device__ unsigned g_is64;

// ======================= small PTX helpers =================================
__device__ __forceinline__ uint32_t smem_u32(const void* p) {
    uint32_t a;
    asm("{ .reg .u64 t; cvta.to.shared.u64 t, %1; cvt.u32.u64 %0, t; }"
        : "=r"(a) : "l"(p));
    return a;
}
#define FMA2(acc_, a_, b_) \
    asm("fma.rn.f32x2 %0, %1, %2, %0;" : "+l"(acc_) : "l"(a_), "l"(b_))
#define UNPK(lo_, hi_, p_) \
    asm("mov.b64 {%0, %1}, %2;" : "=r"(lo_), "=r"(hi_) : "l"(p_))
#define CP_WAIT0() asm volatile("cp.async.wait_group 0;" ::: "memory")
#define CP_WAIT1() asm volatile("cp.async.wait_group 1;" ::: "memory")

template <int CO>
__device__ __forceinline__ void prefetch_w(uint32_t wb_dst, const float* __restrict__ Wsrc,
                                           int kb, int tid) {
    constexpr int IT = (32 * CO / 4) / 256;
    const float* base = Wsrc + (long long)kb * 32 * CO;
#pragma unroll
    for (int t = 0; t < IT; ++t) {
        int idx = tid + t * 256;
        int row = idx / (CO / 4);
        int c4  = idx % (CO / 4);
        uint32_t dst = wb_dst + (uint32_t)(row * CO + c4 * 4) * 4u;
        const float* src = base + row * CO + c4 * 4;
        asm volatile("cp.async.cg.shared.global [%0], [%1], 16;" :: "r"(dst), "l"(src));
    }
    asm volatile("cp.async.commit_group;" ::: "memory");
}

// ======================= CSR build =========================================
__global__ void detect_zero_kernel(const unsigned* __restrict__ ei_u32,
                                   int* __restrict__ deg, int N) {
    int i = blockIdx.x * blockDim.x + threadIdx.x;
    if (i < N) deg[i] = 0;
    if (blockIdx.x == gridDim.x - 1 && threadIdx.x < 32) {
        unsigned acc = 0;
#pragma unroll
        for (int t = 0; t < 16; ++t)
            acc |= ei_u32[2 * (threadIdx.x + t * 32) + 1];
#pragma unroll
        for (int o = 16; o > 0; o >>= 1)
            acc |= __shfl_down_sync(0xffffffffu, acc, o);
        if (threadIdx.x == 0) g_is64 = (acc == 0u) ? 1u : 0u;
    }
}
__global__ void hist_kernel(const void* __restrict__ ei, int* __restrict__ deg, int E) {
    int e = blockIdx.x * blockDim.x + threadIdx.x;
    if (e >= E) return;
    int d = g_is64 ? (int)((const long long*)ei)[E + e] : ((const int*)ei)[E + e];
    atomicAdd(&deg[d], 1);
}
__global__ void scan1_kernel(const int* __restrict__ deg, int* __restrict__ offs,
                             int* __restrict__ part, int N) {
    __shared__ int wsum[32];
    const int tid = threadIdx.x, lane = tid & 31, wid = tid >> 5;
    int i = blockIdx.x * SCAN_BS + tid;
    int v = (i < N) ? deg[i] : 0;
    int x = v;
#pragma unroll
    for (int o = 1; o < 32; o <<= 1) {
        int y = __shfl_up_sync(0xffffffffu, x, o);
        if (lane >= o) x += y;
    }
    if (lane == 31) wsum[wid] = x;
    __syncthreads();
    if (wid == 0) {
        int w = wsum[lane];
#pragma unroll
        for (int o = 1; o < 32; o <<= 1) {
            int y = __shfl_up_sync(0xffffffffu, w, o);
            if (lane >= o) w += y;
        }
        wsum[lane] = w;
    }
    __syncthreads();
    int warpoff = (wid > 0) ? wsum[wid - 1] : 0;
    if (i < N) offs[i] = warpoff + x - v;
    if (tid == SCAN_BS - 1) part[blockIdx.x] = warpoff + x;
}
__global__ void scan23_kernel(int* __restrict__ offs, int* __restrict__ cursor,
                              const int* __restrict__ part, int nblk, int N) {
    __shared__ int soff;
    const int tid = threadIdx.x;
    if (tid < 32) {
        int s = 0;
        for (int j = tid; j < nblk; j += 32)
            if (j < (int)blockIdx.x) s += part[j];
#pragma unroll
        for (int o = 16; o > 0; o >>= 1) s += __shfl_down_sync(0xffffffffu, s, o);
        if (tid == 0) soff = s;
    }
    __syncthreads();
    int i = blockIdx.x * SCAN_BS + tid;
    if (i < N) {
        int v = offs[i] + soff;
        offs[i] = v;
        cursor[i] = v;
    }
    if (blockIdx.x == gridDim.x - 1 && tid < 32) {
        int s = 0;
        for (int j = tid; j < nblk; j += 32) s += part[j];
#pragma unroll
        for (int o = 16; o > 0; o >>= 1) s += __shfl_down_sync(0xffffffffu, s, o);
        if (tid == 0) offs[N] = s;
    }
}
__global__ void fill_kernel(const void* __restrict__ ei, int* __restrict__ cursor,
                            int* __restrict__ csr, int E) {
    int e = blockIdx.x * blockDim.x + threadIdx.x;
    if (e >= E) return;
    int s, d;
    if (g_is64) {
        const long long* p = (const long long*)ei;
        s = (int)p[e];
        d = (int)p[E + e];
    } else {
        const int* p = (const int*)ei;
        s = p[e];
        d = p[E + e];
    }
    int pos = atomicAdd(&cursor[d], 1);
    csr[pos] = s;
}

// ======================= gathers (8/1 unrolled) ============================
__global__ void gather64_kernel(const float* __restrict__ feat,
                                const int* __restrict__ offs,
                                const int* __restrict__ csr,
                                float* __restrict__ out, int N) {
    int t = blockIdx.x * blockDim.x + threadIdx.x;
    int node = t >> 4;
    int lane = threadIdx.x & 15;
    if (node >= N) return;
    int s = offs[node], e = offs[node + 1];
    const float4* f4 = (const float4*)feat;
    float4 acc = f4[(long long)node * 16 + lane];
    int k = s;
    for (; k + 7 < e; k += 8) {
        int j[8];
#pragma unroll
        for (int u = 0; u < 8; ++u) j[u] = __ldg(&csr[k + u]);
        float4 v[8];
#pragma unroll
        for (int u = 0; u < 8; ++u) v[u] = f4[(long long)j[u] * 16 + lane];
#pragma unroll
        for (int u = 0; u < 8; ++u) {
            acc.x += v[u].x; acc.y += v[u].y; acc.z += v[u].z; acc.w += v[u].w;
        }
    }
    for (; k < e; ++k) {
        int j = __ldg(&csr[k]);
        float4 v = f4[(long long)j * 16 + lane];
        acc.x += v.x; acc.y += v.y; acc.z += v.z; acc.w += v.w;
    }
    ((float4*)out)[(long long)node * 16 + lane] = acc;
}
__global__ void gather128_kernel(const float* __restrict__ feat,
                                 const int* __restrict__ offs,
                                 const int* __restrict__ csr,
                                 float* __restrict__ out, int N) {
    int node = (int)((blockIdx.x * blockDim.x + threadIdx.x) >> 5);
    int lane = threadIdx.x & 31;
    if (node >= N) return;
    int s = offs[node], e = offs[node + 1];
    const float4* f4 = (const float4*)feat;
    float4 acc = f4[(long long)node * 32 + lane];
    int k = s;
    for (; k + 7 < e; k += 8) {
        int j[8];
#pragma unroll
        for (int u = 0; u < 8; ++u) j[u] = __ldg(&csr[k + u]);
        float4 v[8];
#pragma unroll
        for (int u = 0; u < 8; ++u) v[u] = f4[(long long)j[u] * 32 + lane];
#pragma unroll
        for (int u = 0; u < 8; ++u) {
            acc.x += v[u].x; acc.y += v[u].y; acc.z += v[u].z; acc.w += v[u].w;
        }
    }
    for (; k < e; ++k) {
        int j = __ldg(&csr[k]);
        float4 v = f4[(long long)j * 32 + lane];
        acc.x += v.x; acc.y += v.y; acc.z += v.z; acc.w += v.w;
    }
    ((float4*)out)[(long long)node * 32 + lane] = acc;
}

// ======================= fused 2-GEMM MLP ==================================
// Out[N,CO2] = act2(relu(A[N,CI] @ W1[CI,128] + b1) @ W2[128,CO2] + b2)
// As/T1 alias the same SMEM. 2-deep cp.async pipeline: blocks 0+1 prefetched
// before each stage's loop; kb+2 prefetched into the just-freed buffer.
template <int CI, int CO2, int RELU2>
__global__ void __launch_bounds__(256, 2)
mlp_fused_kernel(const float* __restrict__ A,
                 const float* __restrict__ W1, const float* __restrict__ b1,
                 const float* __restrict__ W2, const float* __restrict__ b2,
                 float* __restrict__ Out, int Nrows) {
    constexpr int SA  = 132;
    constexpr int KB1 = CI / 32;
    constexpr int KB2 = 128 / 32;
    constexpr int NG  = CO2 / 64;

    extern __shared__ float sm[];
    float* As = sm;                    // CI x SA   (aliases T1)
    float* T1 = sm;                    // 128 x SA
    float* Wb = sm + 128 * SA;         // 2 x 32 x 128 W double buffer
    const uint32_t wb_addr = smem_u32(Wb);
    constexpr uint32_t WBUF_BYTES = 32 * 128 * 4;

    const int tid = threadIdx.x;
    const int tr  = tid >> 4;
    const int tc  = tid & 15;
    const long long rowBase = (long long)blockIdx.x * 64;

    prefetch_w<128>(wb_addr, W1, 0, tid);

    // ---- load A tile, splat-transpose into As ----
    constexpr int QA = CI / 4;
#pragma unroll
    for (int t = 0; t < 64 * QA / 256; ++t) {
        int idx = tid + t * 256;
        int m = idx / QA, q = idx % QA;
        long long row = rowBase + m;
        float4 v = make_float4(0.f, 0.f, 0.f, 0.f);
        if (row < Nrows) v = ((const float4*)(A + row * CI))[q];
        *(float2*)&As[(q * 4 + 0) * SA + 2 * m] = make_float2(v.x, v.x);
        *(float2*)&As[(q * 4 + 1) * SA + 2 * m] = make_float2(v.y, v.y);
        *(float2*)&As[(q * 4 + 2) * SA + 2 * m] = make_float2(v.z, v.z);
        *(float2*)&As[(q * 4 + 3) * SA + 2 * m] = make_float2(v.w, v.w);
    }
    if (KB1 > 1) prefetch_w<128>(wb_addr + WBUF_BYTES, W1, 1, tid);

    unsigned long long acc[4][4];
#pragma unroll
    for (int i = 0; i < 4; ++i)
#pragma unroll
        for (int j = 0; j < 4; ++j) acc[i][j] = 0ull;

    // ---------------- stage 1: acc = A @ W1 ----------------
#pragma unroll
    for (int kb = 0; kb < KB1; ++kb) {
        if (kb == KB1 - 1) { CP_WAIT0(); } else { CP_WAIT1(); }
        __syncthreads();
        const float* Bs  = Wb + (kb & 1) * (32 * 128);
        const float* Asb = As + kb * 32 * SA;
#pragma unroll
        for (int k = 0; k < 32; ++k) {
            ulonglong2 aa = *(const ulonglong2*)&Asb[k * SA + tr * 8];
            ulonglong2 ab = *(const ulonglong2*)&Asb[k * SA + tr * 8 + 4];
            ulonglong2 b0 = *(const ulonglong2*)&Bs[k * 128 + tc * 4];
            ulonglong2 b1v = *(const ulonglong2*)&Bs[k * 128 + 64 + tc * 4];
            FMA2(acc[0][0], aa.x, b0.x); FMA2(acc[0][1], aa.x, b0.y);
            FMA2(acc[0][2], aa.x, b1v.x); FMA2(acc[0][3], aa.x, b1v.y);
            FMA2(acc[1][0], aa.y, b0.x); FMA2(acc[1][1], aa.y, b0.y);
            FMA2(acc[1][2], aa.y, b1v.x); FMA2(acc[1][3], aa.y, b1v.y);
            FMA2(acc[2][0], ab.x, b0.x); FMA2(acc[2][1], ab.x, b0.y);
            FMA2(acc[2][2], ab.x, b1v.x); FMA2(acc[2][3], ab.x, b1v.y);
            FMA2(acc[3][0], ab.y, b0.x); FMA2(acc[3][1], ab.y, b0.y);
            FMA2(acc[3][2], ab.y, b1v.x); FMA2(acc[3][3], ab.y, b1v.y);
        }
        __syncthreads();   // buffer kb&1 now free; As reads done (T1 alias ok)
        if (kb + 2 < KB1) prefetch_w<128>(wb_addr + (kb & 1) * WBUF_BYTES, W1, kb + 2, tid);
    }

    // Both W2 blocks stream while the stage-1 epilogue runs.
    prefetch_w<CO2>(wb_addr, W2, 0, tid);
    prefetch_w<CO2>(wb_addr + WBUF_BYTES, W2, 1, tid);

    // ---- stage-1 epilogue: bias + relu, splat into T1 (aliasing As) ----
    {
        float bb[8];
#pragma unroll
        for (int e = 0; e < 4; ++e) {
            bb[e]     = __ldg(&b1[tc * 4 + e]);
            bb[4 + e] = __ldg(&b1[64 + tc * 4 + e]);
        }
#pragma unroll
        for (int i = 0; i < 4; ++i) {
            int m2 = 2 * (tr * 4 + i);
#pragma unroll
            for (int g = 0; g < 2; ++g)
#pragma unroll
                for (int jp = 0; jp < 2; ++jp) {
                    uint32_t lo, hi;
                    UNPK(lo, hi, acc[i][g * 2 + jp]);
                    float v0 = fmaxf(__uint_as_float(lo) + bb[g * 4 + jp * 2 + 0], 0.f);
                    float v1 = fmaxf(__uint_as_float(hi) + bb[g * 4 + jp * 2 + 1], 0.f);
                    int c = g * 64 + tc * 4 + jp * 2;
                    *(float2*)&T1[(c + 0) * SA + m2] = make_float2(v0, v0);
                    *(float2*)&T1[(c + 1) * SA + m2] = make_float2(v1, v1);
                }
        }
    }
    __syncthreads();

    // ---------------- stage 2: out = T1 @ W2 ----------------
    unsigned long long acc2[4][2 * NG];
#pragma unroll
    for (int i = 0; i < 4; ++i)
#pragma unroll
        for (int j = 0; j < 2 * NG; ++j) acc2[i][j] = 0ull;

#pragma unroll
    for (int kb = 0; kb < KB2; ++kb) {
        if (kb == KB2 - 1) { CP_WAIT0(); } else { CP_WAIT1(); }
        __syncthreads();
        const float* Bs = Wb + (kb & 1) * (32 * 128);
        const float* Tb = T1 + kb * 32 * SA;
#pragma unroll
        for (int k = 0; k < 32; ++k) {
            ulonglong2 aa = *(const ulonglong2*)&Tb[k * SA + tr * 8];
            ulonglong2 ab = *(const ulonglong2*)&Tb[k * SA + tr * 8 + 4];
            ulonglong2 b0 = *(const ulonglong2*)&Bs[k * CO2 + tc * 4];
            FMA2(acc2[0][0], aa.x, b0.x); FMA2(acc2[0][1], aa.x, b0.y);
            FMA2(acc2[1][0], aa.y, b0.x); FMA2(acc2[1][1], aa.y, b0.y);
            FMA2(acc2[2][0], ab.x, b0.x); FMA2(acc2[2][1], ab.x, b0.y);
            FMA2(acc2[3][0], ab.y, b0.x); FMA2(acc2[3][1], ab.y, b0.y);
            if (NG == 2) {
                ulonglong2 b1v = *(const ulonglong2*)&Bs[k * CO2 + 64 + tc * 4];
                FMA2(acc2[0][2], aa.x, b1v.x); FMA2(acc2[0][3], aa.x, b1v.y);
                FMA2(acc2[1][2], aa.y, b1v.x); FMA2(acc2[1][3], aa.y, b1v.y);
                FMA2(acc2[2][2], ab.x, b1v.x); FMA2(acc2[2][3], ab.x, b1v.y);
                FMA2(acc2[3][2], ab.y, b1v.x); FMA2(acc2[3][3], ab.y, b1v.y);
            }
        }
        __syncthreads();
        if (kb + 2 < KB2) prefetch_w<CO2>(wb_addr + (kb & 1) * WBUF_BYTES, W2, kb + 2, tid);
    }

    // ---- final epilogue ----
    {
        float bb[4 * NG];
#pragma unroll
        for (int g = 0; g < NG; ++g)
#pragma unroll
            for (int e = 0; e < 4; ++e)
                bb[g * 4 + e] = __ldg(&b2[g * 64 + tc * 4 + e]);
#pragma unroll
        for (int i = 0; i < 4; ++i) {
            long long row = rowBase + tr * 4 + i;
            if (row >= Nrows) continue;
#pragma unroll
            for (int g = 0; g < NG; ++g) {
                uint32_t l0, h0, l1, h1;
                UNPK(l0, h0, acc2[i][g * 2 + 0]);
                UNPK(l1, h1, acc2[i][g * 2 + 1]);
                float4 o;
                o.x = __uint_as_float(l0) + bb[g * 4 + 0];
                o.y = __uint_as_float(h0) + bb[g * 4 + 1];
                o.z = __uint_as_float(l1) + bb[g * 4 + 2];
                o.w = __uint_as_float(h1) + bb[g * 4 + 3];
                if (RELU2) {
                    o.x = fmaxf(o.x, 0.f); o.y = fmaxf(o.y, 0.f);
                    o.z = fmaxf(o.z, 0.f); o.w = fmaxf(o.w, 0.f);
                }
                *(float4*)(Out + row * CO2 + g * 64 + tc * 4) = o;
            }
        }
    }
}

// ---------------------------------------------------------------------------
extern "C" void kernel_launch(void* const* d_in, const int* in_sizes, int n_in,
                              void* d_out, int out_size) {
    const float* x  = (const float*)d_in[0];
    const void*  ei = d_in[1];
    const float* W1 = (const float*)d_in[2];
    const float* b1 = (const float*)d_in[3];
    const float* W2 = (const float*)d_in[4];
    const float* b2 = (const float*)d_in[5];
    const float* W3 = (const float*)d_in[6];
    const float* b3 = (const float*)d_in[7];
    const float* W4 = (const float*)d_in[8];
    const float* b4 = (const float*)d_in[9];

    const int N = in_sizes[0] / CIN;
    const int E = in_sizes[1] / 2;

    float *h1pre, *h, *h2pre;
    cudaGetSymbolAddress((void**)&h1pre, g_h1pre);
    cudaGetSymbolAddress((void**)&h,     g_h);
    cudaGetSymbolAddress((void**)&h2pre, g_h2pre);
    int *deg, *offs, *cursor, *csr, *part;
    cudaGetSymbolAddress((void**)&deg,    g_deg);
    cudaGetSymbolAddress((void**)&offs,   g_offs);
    cudaGetSymbolAddress((void**)&cursor, g_cursor);
    cudaGetSymbolAddress((void**)&csr,    g_csr);
    cudaGetSymbolAddress((void**)&part,   g_part);

    float* out = (float*)d_out;
    const int rtiles      = (N + 63) / 64;
    const int edge_blocks = (E + 255) / 256;
    const int scan_blocks = (N + SCAN_BS - 1) / SCAN_BS;
    const int g64_blocks  = (N * 16 + 255) / 256;
    const int g128_blocks = (N * 32 + 255) / 256;

    const int smem_mlp = (128 * 132 + 2 * 32 * 128) * 4;   // ~100 KB
    cudaFuncSetAttribute(mlp_fused_kernel<CIN,  CHID, 1>,
                         cudaFuncAttributeMaxDynamicSharedMemorySize, smem_mlp);
    cudaFuncSetAttribute(mlp_fused_kernel<CHID, CIN,  0>,
                         cudaFuncAttributeMaxDynamicSharedMemorySize, smem_mlp);

    // ---- CSR build (5 launches) ----
    detect_zero_kernel<<<(N + 255) / 256, 256>>>((const unsigned*)ei, deg, N);
    hist_kernel<<<edge_blocks, 256>>>(ei, deg, E);
    scan1_kernel<<<scan_blocks, SCAN_BS>>>(deg, offs, part, N);
    scan23_kernel<<<scan_blocks, SCAN_BS>>>(offs, cursor, part, scan_blocks, N);
    fill_kernel<<<edge_blocks, 256>>>(ei, cursor, csr, E);

    // ---- Layer 1 ----
    gather64_kernel<<<g64_blocks, 256>>>(x, offs, csr, h1pre, N);
    mlp_fused_kernel<CIN,  CHID, 1><<<rtiles, 256, smem_mlp>>>(h1pre, W1, b1, W2, b2, h, N);

    // ---- Layer 2 ----
    gather128_kernel<<<g128_blocks, 256>>>(h, offs, csr, h2pre, N);
    mlp_fused_kernel<CHID, CIN,  0><<<rtiles, 256, smem_mlp>>>(h2pre, W3, b3, W4, b4, out, N);
}

// round 13
// speedup vs baseline: 1.1697x; 1.1543x over previous
#include <cuda_runtime.h>
#include <cstdint>

// ---------------------------------------------------------------------------
// GIN (2 layers) on GB300 — CSR-gather aggregation + fused 2-GEMM MLP kernels.
// f32x2 (FFMA2) microkernels with register splat-packing (unsplatted SMEM
// tiles -> 66KB -> 3 CTAs/SM), 2-deep cp.async W pipeline, As/T1 aliasing.
// ---------------------------------------------------------------------------

#define NMAX 50000
#define EMAX 800000
#define CIN  64
#define CHID 128
#define SCAN_BS 1024
#define MAXPART 256

__device__ float g_h1pre[NMAX * CIN];
__device__ float g_h    [NMAX * CHID];
__device__ float g_h2pre[NMAX * CHID];

__device__ int g_deg   [NMAX];
__device__ int g_offs  [NMAX + 1];
__device__ int g_cursor[NMAX];
__device__ int g_csr   [EMAX];
__device__ int g_part  [MAXPART];
__device__ unsigned g_is64;

// ======================= small PTX helpers =================================
__device__ __forceinline__ uint32_t smem_u32(const void* p) {
    uint32_t a;
    asm("{ .reg .u64 t; cvta.to.shared.u64 t, %1; cvt.u32.u64 %0, t; }"
        : "=r"(a) : "l"(p));
    return a;
}
#define FMA2(acc_, a_, b_) \
    asm("fma.rn.f32x2 %0, %1, %2, %0;" : "+l"(acc_) : "l"(a_), "l"(b_))
#define PACK2(dst_, v_) \
    asm("mov.b64 %0, {%1, %1};" : "=l"(dst_) : "r"(__float_as_uint(v_)))
#define UNPK(lo_, hi_, p_) \
    asm("mov.b64 {%0, %1}, %2;" : "=r"(lo_), "=r"(hi_) : "l"(p_))
#define CP_WAIT0() asm volatile("cp.async.wait_group 0;" ::: "memory")
#define CP_WAIT1() asm volatile("cp.async.wait_group 1;" ::: "memory")

template <int CO>
__device__ __forceinline__ void prefetch_w(uint32_t wb_dst, const float* __restrict__ Wsrc,
                                           int kb, int tid) {
    constexpr int IT = (32 * CO / 4) / 256;
    const float* base = Wsrc + (long long)kb * 32 * CO;
#pragma unroll
    for (int t = 0; t < IT; ++t) {
        int idx = tid + t * 256;
        int row = idx / (CO / 4);
        int c4  = idx % (CO / 4);
        uint32_t dst = wb_dst + (uint32_t)(row * CO + c4 * 4) * 4u;
        const float* src = base + row * CO + c4 * 4;
        asm volatile("cp.async.cg.shared.global [%0], [%1], 16;" :: "r"(dst), "l"(src));
    }
    asm volatile("cp.async.commit_group;" ::: "memory");
}

// ======================= CSR build =========================================
__global__ void detect_zero_kernel(const unsigned* __restrict__ ei_u32,
                                   int* __restrict__ deg, int N) {
    int i = blockIdx.x * blockDim.x + threadIdx.x;
    if (i < N) deg[i] = 0;
    if (blockIdx.x == gridDim.x - 1 && threadIdx.x < 32) {
        unsigned acc = 0;
#pragma unroll
        for (int t = 0; t < 16; ++t)
            acc |= ei_u32[2 * (threadIdx.x + t * 32) + 1];
#pragma unroll
        for (int o = 16; o > 0; o >>= 1)
            acc |= __shfl_down_sync(0xffffffffu, acc, o);
        if (threadIdx.x == 0) g_is64 = (acc == 0u) ? 1u : 0u;
    }
}
__global__ void hist_kernel(const void* __restrict__ ei, int* __restrict__ deg, int E) {
    int e = blockIdx.x * blockDim.x + threadIdx.x;
    if (e >= E) return;
    int d = g_is64 ? (int)((const long long*)ei)[E + e] : ((const int*)ei)[E + e];
    atomicAdd(&deg[d], 1);
}
__global__ void scan1_kernel(const int* __restrict__ deg, int* __restrict__ offs,
                             int* __restrict__ part, int N) {
    __shared__ int wsum[32];
    const int tid = threadIdx.x, lane = tid & 31, wid = tid >> 5;
    int i = blockIdx.x * SCAN_BS + tid;
    int v = (i < N) ? deg[i] : 0;
    int x = v;
#pragma unroll
    for (int o = 1; o < 32; o <<= 1) {
        int y = __shfl_up_sync(0xffffffffu, x, o);
        if (lane >= o) x += y;
    }
    if (lane == 31) wsum[wid] = x;
    __syncthreads();
    if (wid == 0) {
        int w = wsum[lane];
#pragma unroll
        for (int o = 1; o < 32; o <<= 1) {
            int y = __shfl_up_sync(0xffffffffu, w, o);
            if (lane >= o) w += y;
        }
        wsum[lane] = w;
    }
    __syncthreads();
    int warpoff = (wid > 0) ? wsum[wid - 1] : 0;
    if (i < N) offs[i] = warpoff + x - v;
    if (tid == SCAN_BS - 1) part[blockIdx.x] = warpoff + x;
}
__global__ void scan23_kernel(int* __restrict__ offs, int* __restrict__ cursor,
                              const int* __restrict__ part, int nblk, int N) {
    __shared__ int soff;
    const int tid = threadIdx.x;
    if (tid < 32) {
        int s = 0;
        for (int j = tid; j < nblk; j += 32)
            if (j < (int)blockIdx.x) s += part[j];
#pragma unroll
        for (int o = 16; o > 0; o >>= 1) s += __shfl_down_sync(0xffffffffu, s, o);
        if (tid == 0) soff = s;
    }
    __syncthreads();
    int i = blockIdx.x * SCAN_BS + tid;
    if (i < N) {
        int v = offs[i] + soff;
        offs[i] = v;
        cursor[i] = v;
    }
    if (blockIdx.x == gridDim.x - 1 && tid < 32) {
        int s = 0;
        for (int j = tid; j < nblk; j += 32) s += part[j];
#pragma unroll
        for (int o = 16; o > 0; o >>= 1) s += __shfl_down_sync(0xffffffffu, s, o);
        if (tid == 0) offs[N] = s;
    }
}
__global__ void fill_kernel(const void* __restrict__ ei, int* __restrict__ cursor,
                            int* __restrict__ csr, int E) {
    int e = blockIdx.x * blockDim.x + threadIdx.x;
    if (e >= E) return;
    int s, d;
    if (g_is64) {
        const long long* p = (const long long*)ei;
        s = (int)p[e];
        d = (int)p[E + e];
    } else {
        const int* p = (const int*)ei;
        s = p[e];
        d = p[E + e];
    }
    int pos = atomicAdd(&cursor[d], 1);
    csr[pos] = s;
}

// ======================= gathers ===========================================
__global__ void gather64_kernel(const float* __restrict__ feat,
                                const int* __restrict__ offs,
                                const int* __restrict__ csr,
                                float* __restrict__ out, int N) {
    int t = blockIdx.x * blockDim.x + threadIdx.x;
    int node = t >> 4;
    int lane = threadIdx.x & 15;
    if (node >= N) return;
    int s = offs[node], e = offs[node + 1];
    const float4* f4 = (const float4*)feat;
    float4 acc = f4[(long long)node * 16 + lane];
    int k = s;
    for (; k + 7 < e; k += 8) {
        int j[8];
#pragma unroll
        for (int u = 0; u < 8; ++u) j[u] = __ldg(&csr[k + u]);
        float4 v[8];
#pragma unroll
        for (int u = 0; u < 8; ++u) v[u] = f4[(long long)j[u] * 16 + lane];
#pragma unroll
        for (int u = 0; u < 8; ++u) {
            acc.x += v[u].x; acc.y += v[u].y; acc.z += v[u].z; acc.w += v[u].w;
        }
    }
    for (; k < e; ++k) {
        int j = __ldg(&csr[k]);
        float4 v = f4[(long long)j * 16 + lane];
        acc.x += v.x; acc.y += v.y; acc.z += v.z; acc.w += v.w;
    }
    ((float4*)out)[(long long)node * 16 + lane] = acc;
}
__global__ void gather128_kernel(const float* __restrict__ feat,
                                 const int* __restrict__ offs,
                                 const int* __restrict__ csr,
                                 float* __restrict__ out, int N) {
    int node = (int)((blockIdx.x * blockDim.x + threadIdx.x) >> 5);
    int lane = threadIdx.x & 31;
    if (node >= N) return;
    int s = offs[node], e = offs[node + 1];
    const float4* f4 = (const float4*)feat;
    float4 acc = f4[(long long)node * 32 + lane];
    int k = s;
    for (; k + 7 < e; k += 8) {
        int j[8];
#pragma unroll
        for (int u = 0; u < 8; ++u) j[u] = __ldg(&csr[k + u]);
        float4 v[8];
#pragma unroll
        for (int u = 0; u < 8; ++u) v[u] = f4[(long long)j[u] * 32 + lane];
#pragma unroll
        for (int u = 0; u < 8; ++u) {
            acc.x += v[u].x; acc.y += v[u].y; acc.z += v[u].z; acc.w += v[u].w;
        }
    }
    for (; k < e; ++k) {
        int j = __ldg(&csr[k]);
        float4 v = f4[(long long)j * 32 + lane];
        acc.x += v.x; acc.y += v.y; acc.z += v.z; acc.w += v.w;
    }
    ((float4*)out)[(long long)node * 32 + lane] = acc;
}

// ======================= fused 2-GEMM MLP ==================================
// Out[N,CO2] = act2(relu(A[N,CI] @ W1[CI,128] + b1) @ W2[128,CO2] + b2)
// Unsplatted k-major tiles (stride 68 floats); splat via mov.b64 in registers
// (idle issue slots — FMA2 rt binds). 66KB smem -> 3 CTAs/SM.
template <int CI, int CO2, int RELU2>
__global__ void __launch_bounds__(256, 3)
mlp_fused_kernel(const float* __restrict__ A,
                 const float* __restrict__ W1, const float* __restrict__ b1,
                 const float* __restrict__ W2, const float* __restrict__ b2,
                 float* __restrict__ Out, int Nrows) {
    constexpr int SA  = 68;            // row stride (floats), 16B-aligned
    constexpr int KB1 = CI / 32;
    constexpr int KB2 = 128 / 32;
    constexpr int NG  = CO2 / 64;

    extern __shared__ float sm[];
    float* As = sm;                    // CI x SA   (aliases T1)
    float* T1 = sm;                    // 128 x SA
    float* Wb = sm + 128 * SA;         // 2 x 32 x 128 W double buffer
    const uint32_t wb_addr = smem_u32(Wb);
    constexpr uint32_t WBUF_BYTES = 32 * 128 * 4;

    const int tid = threadIdx.x;
    const int tr  = tid >> 4;
    const int tc  = tid & 15;
    const long long rowBase = (long long)blockIdx.x * 64;

    prefetch_w<128>(wb_addr, W1, 0, tid);

    // ---- load A tile, transpose into As (k-major, unsplatted) ----
    constexpr int QA = CI / 4;
#pragma unroll
    for (int t = 0; t < 64 * QA / 256; ++t) {
        int idx = tid + t * 256;
        int m = idx / QA, q = idx % QA;
        long long row = rowBase + m;
        float4 v = make_float4(0.f, 0.f, 0.f, 0.f);
        if (row < Nrows) v = ((const float4*)(A + row * CI))[q];
        As[(q * 4 + 0) * SA + m] = v.x;
        As[(q * 4 + 1) * SA + m] = v.y;
        As[(q * 4 + 2) * SA + m] = v.z;
        As[(q * 4 + 3) * SA + m] = v.w;
    }
    if (KB1 > 1) prefetch_w<128>(wb_addr + WBUF_BYTES, W1, 1, tid);

    unsigned long long acc[4][4];
#pragma unroll
    for (int i = 0; i < 4; ++i)
#pragma unroll
        for (int j = 0; j < 4; ++j) acc[i][j] = 0ull;

    // ---------------- stage 1: acc = A @ W1 ----------------
#pragma unroll
    for (int kb = 0; kb < KB1; ++kb) {
        if (kb == KB1 - 1) { CP_WAIT0(); } else { CP_WAIT1(); }
        __syncthreads();
        const float* Bs  = Wb + (kb & 1) * (32 * 128);
        const float* Asb = As + kb * 32 * SA;
#pragma unroll
        for (int k = 0; k < 32; ++k) {
            float4 av = *(const float4*)&Asb[k * SA + tr * 4];
            unsigned long long ap0, ap1, ap2, ap3;
            PACK2(ap0, av.x); PACK2(ap1, av.y);
            PACK2(ap2, av.z); PACK2(ap3, av.w);
            ulonglong2 b0 = *(const ulonglong2*)&Bs[k * 128 + tc * 4];
            ulonglong2 b1v = *(const ulonglong2*)&Bs[k * 128 + 64 + tc * 4];
            FMA2(acc[0][0], ap0, b0.x); FMA2(acc[0][1], ap0, b0.y);
            FMA2(acc[0][2], ap0, b1v.x); FMA2(acc[0][3], ap0, b1v.y);
            FMA2(acc[1][0], ap1, b0.x); FMA2(acc[1][1], ap1, b0.y);
            FMA2(acc[1][2], ap1, b1v.x); FMA2(acc[1][3], ap1, b1v.y);
            FMA2(acc[2][0], ap2, b0.x); FMA2(acc[2][1], ap2, b0.y);
            FMA2(acc[2][2], ap2, b1v.x); FMA2(acc[2][3], ap2, b1v.y);
            FMA2(acc[3][0], ap3, b0.x); FMA2(acc[3][1], ap3, b0.y);
            FMA2(acc[3][2], ap3, b1v.x); FMA2(acc[3][3], ap3, b1v.y);
        }
        __syncthreads();   // buffer kb&1 free; As reads done (T1 alias ok)
        if (kb + 2 < KB1) prefetch_w<128>(wb_addr + (kb & 1) * WBUF_BYTES, W1, kb + 2, tid);
    }

    // Both W2 blocks stream while the stage-1 epilogue runs.
    prefetch_w<CO2>(wb_addr, W2, 0, tid);
    prefetch_w<CO2>(wb_addr + WBUF_BYTES, W2, 1, tid);

    // ---- stage-1 epilogue: bias + relu into T1 (aliasing As) ----
    {
        float bb[8];
#pragma unroll
        for (int e = 0; e < 4; ++e) {
            bb[e]     = __ldg(&b1[tc * 4 + e]);
            bb[4 + e] = __ldg(&b1[64 + tc * 4 + e]);
        }
#pragma unroll
        for (int i = 0; i < 4; ++i) {
            int m = tr * 4 + i;
#pragma unroll
            for (int g = 0; g < 2; ++g)
#pragma unroll
                for (int jp = 0; jp < 2; ++jp) {
                    uint32_t lo, hi;
                    UNPK(lo, hi, acc[i][g * 2 + jp]);
                    float v0 = fmaxf(__uint_as_float(lo) + bb[g * 4 + jp * 2 + 0], 0.f);
                    float v1 = fmaxf(__uint_as_float(hi) + bb[g * 4 + jp * 2 + 1], 0.f);
                    int c = g * 64 + tc * 4 + jp * 2;
                    T1[(c + 0) * SA + m] = v0;
                    T1[(c + 1) * SA + m] = v1;
                }
        }
    }
    __syncthreads();

    // ---------------- stage 2: out = T1 @ W2 ----------------
    unsigned long long acc2[4][2 * NG];
#pragma unroll
    for (int i = 0; i < 4; ++i)
#pragma unroll
        for (int j = 0; j < 2 * NG; ++j) acc2[i][j] = 0ull;

#pragma unroll
    for (int kb = 0; kb < KB2; ++kb) {
        if (kb == KB2 - 1) { CP_WAIT0(); } else { CP_WAIT1(); }
        __syncthreads();
        const float* Bs = Wb + (kb & 1) * (32 * 128);
        const float* Tb = T1 + kb * 32 * SA;
#pragma unroll
        for (int k = 0; k < 32; ++k) {
            float4 av = *(const float4*)&Tb[k * SA + tr * 4];
            unsigned long long ap0, ap1, ap2, ap3;
            PACK2(ap0, av.x); PACK2(ap1, av.y);
            PACK2(ap2, av.z); PACK2(ap3, av.w);
            ulonglong2 b0 = *(const ulonglong2*)&Bs[k * CO2 + tc * 4];
            FMA2(acc2[0][0], ap0, b0.x); FMA2(acc2[0][1], ap0, b0.y);
            FMA2(acc2[1][0], ap1, b0.x); FMA2(acc2[1][1], ap1, b0.y);
            FMA2(acc2[2][0], ap2, b0.x); FMA2(acc2[2][1], ap2, b0.y);
            FMA2(acc2[3][0], ap3, b0.x); FMA2(acc2[3][1], ap3, b0.y);
            if (NG == 2) {
                ulonglong2 b1v = *(const ulonglong2*)&Bs[k * CO2 + 64 + tc * 4];
                FMA2(acc2[0][2], ap0, b1v.x); FMA2(acc2[0][3], ap0, b1v.y);
                FMA2(acc2[1][2], ap1, b1v.x); FMA2(acc2[1][3], ap1, b1v.y);
                FMA2(acc2[2][2], ap2, b1v.x); FMA2(acc2[2][3], ap2, b1v.y);
                FMA2(acc2[3][2], ap3, b1v.x); FMA2(acc2[3][3], ap3, b1v.y);
            }
        }
        __syncthreads();
        if (kb + 2 < KB2) prefetch_w<CO2>(wb_addr + (kb & 1) * WBUF_BYTES, W2, kb + 2, tid);
    }

    // ---- final epilogue ----
    {
        float bb[4 * NG];
#pragma unroll
        for (int g = 0; g < NG; ++g)
#pragma unroll
            for (int e = 0; e < 4; ++e)
                bb[g * 4 + e] = __ldg(&b2[g * 64 + tc * 4 + e]);
#pragma unroll
        for (int i = 0; i < 4; ++i) {
            long long row = rowBase + tr * 4 + i;
            if (row >= Nrows) continue;
#pragma unroll
            for (int g = 0; g < NG; ++g) {
                uint32_t l0, h0, l1, h1;
                UNPK(l0, h0, acc2[i][g * 2 + 0]);
                UNPK(l1, h1, acc2[i][g * 2 + 1]);
                float4 o;
                o.x = __uint_as_float(l0) + bb[g * 4 + 0];
                o.y = __uint_as_float(h0) + bb[g * 4 + 1];
                o.z = __uint_as_float(l1) + bb[g * 4 + 2];
                o.w = __uint_as_float(h1) + bb[g * 4 + 3];
                if (RELU2) {
                    o.x = fmaxf(o.x, 0.f); o.y = fmaxf(o.y, 0.f);
                    o.z = fmaxf(o.z, 0.f); o.w = fmaxf(o.w, 0.f);
                }
                *(float4*)(Out + row * CO2 + g * 64 + tc * 4) = o;
            }
        }
    }
}

// ---------------------------------------------------------------------------
extern "C" void kernel_launch(void* const* d_in, const int* in_sizes, int n_in,
                              void* d_out, int out_size) {
    const float* x  = (const float*)d_in[0];
    const void*  ei = d_in[1];
    const float* W1 = (const float*)d_in[2];
    const float* b1 = (const float*)d_in[3];
    const float* W2 = (const float*)d_in[4];
    const float* b2 = (const float*)d_in[5];
    const float* W3 = (const float*)d_in[6];
    const float* b3 = (const float*)d_in[7];
    const float* W4 = (const float*)d_in[8];
    const float* b4 = (const float*)d_in[9];

    const int N = in_sizes[0] / CIN;
    const int E = in_sizes[1] / 2;

    float *h1pre, *h, *h2pre;
    cudaGetSymbolAddress((void**)&h1pre, g_h1pre);
    cudaGetSymbolAddress((void**)&h,     g_h);
    cudaGetSymbolAddress((void**)&h2pre, g_h2pre);
    int *deg, *offs, *cursor, *csr, *part;
    cudaGetSymbolAddress((void**)&deg,    g_deg);
    cudaGetSymbolAddress((void**)&offs,   g_offs);
    cudaGetSymbolAddress((void**)&cursor, g_cursor);
    cudaGetSymbolAddress((void**)&csr,    g_csr);
    cudaGetSymbolAddress((void**)&part,   g_part);

    float* out = (float*)d_out;
    const int rtiles      = (N + 63) / 64;
    const int edge_blocks = (E + 255) / 256;
    const int scan_blocks = (N + SCAN_BS - 1) / SCAN_BS;
    const int g64_blocks  = (N * 16 + 255) / 256;
    const int g128_blocks = (N * 32 + 255) / 256;

    // Unsplatted As/T1 (128 x 68 floats) + W double buffer -> 66KB.
    const int smem_mlp = (128 * 68 + 2 * 32 * 128) * 4;
    cudaFuncSetAttribute(mlp_fused_kernel<CIN,  CHID, 1>,
                         cudaFuncAttributeMaxDynamicSharedMemorySize, smem_mlp);
    cudaFuncSetAttribute(mlp_fused_kernel<CHID, CIN,  0>,
                         cudaFuncAttributeMaxDynamicSharedMemorySize, smem_mlp);

    // ---- CSR build (5 launches) ----
    detect_zero_kernel<<<(N + 255) / 256, 256>>>((const unsigned*)ei, deg, N);
    hist_kernel<<<edge_blocks, 256>>>(ei, deg, E);
    scan1_kernel<<<scan_blocks, SCAN_BS>>>(deg, offs, part, N);
    scan23_kernel<<<scan_blocks, SCAN_BS>>>(offs, cursor, part, scan_blocks, N);
    fill_kernel<<<edge_blocks, 256>>>(ei, cursor, csr, E);

    // ---- Layer 1 ----
    gather64_kernel<<<g64_blocks, 256>>>(x, offs, csr, h1pre, N);
    mlp_fused_kernel<CIN,  CHID, 1><<<rtiles, 256, smem_mlp>>>(h1pre, W1, b1, W2, b2, h, N);

    // ---- Layer 2 ----
    gather128_kernel<<<g128_blocks, 256>>>(h, offs, csr, h2pre, N);
    mlp_fused_kernel<CHID, CIN,  0><<<rtiles, 256, smem_mlp>>>(h2pre, W3, b3, W4, b4, out, N);
}